// round 15
// baseline (speedup 1.0000x reference)
#include <cuda_runtime.h>
#include <cuda_bf16.h>
#include <cstdint>

#define NN 50000
#define EE 600000
#define DD 128
#define GG 256
#define OO 10
#define LL 5
#define BN_EPS 1e-5f

// Scratch (static device globals — no runtime allocation).
// NOTE: never reference these symbols in HOST code (ATS resolves the host
// shadow silently on GB300). Device code only.
__device__ float g_xcur[NN * DD];
__device__ float g_aggr[NN * DD];
__device__ float g_h1[NN * DD];
__device__ float g_pooled[(LL + 1) * GG * DD];
__device__ float g_counts[GG];

// Packed, pre-split weights: [10][p=64][c=128] uint4 = (bh0,bh1,bl0,bl1),
// p = kk*4 + tig encodes k0 = kk*8 + tig (and k0+4 in .y/.w lanes).
__device__ uint4 g_wpack[LL * 2][64 * DD];

// CSR scratch
__device__ int g_deg[NN];
__device__ int g_off[NN + 1];
__device__ int g_epos[NN];
__device__ int g_bsum[128];
__device__ int g_esrc[EE];
__device__ int g_eattr[EE];   // packed a0 | a1<<3 | a2<<6

#define SCAN_B 512
#define SCAN_NBLK ((NN + SCAN_B - 1) / SCAN_B)   // 98

#define SA_STRIDE 132

// ---------------------------------------------------------------------------
__device__ __forceinline__ uint32_t f2tf32(float f) {
    uint32_t r;
    asm("cvt.rna.tf32.f32 %0, %1;" : "=r"(r) : "f"(f));
    return r;
}

__device__ __forceinline__ void mma_tf32(float* c, const uint32_t* a, uint32_t b0, uint32_t b1) {
    asm volatile(
        "mma.sync.aligned.m16n8k8.row.col.f32.tf32.tf32.f32 "
        "{%0,%1,%2,%3}, {%4,%5,%6,%7}, {%8,%9}, {%0,%1,%2,%3};"
        : "+f"(c[0]), "+f"(c[1]), "+f"(c[2]), "+f"(c[3])
        : "r"(a[0]), "r"(a[1]), "r"(a[2]), "r"(a[3]), "r"(b0), "r"(b1));
}

__device__ __forceinline__ void red_v4(float* addr, float x, float y, float z, float w) {
    asm volatile("red.global.add.v4.f32 [%0], {%1,%2,%3,%4};"
                 :: "l"(addr), "f"(x), "f"(y), "f"(z), "f"(w) : "memory");
}

__device__ __forceinline__ void red_v2(float* addr, float x, float y) {
    asm volatile("red.global.add.v2.f32 [%0], {%1,%2};"
                 :: "l"(addr), "f"(x), "f"(y) : "memory");
}

// ---------------------------------------------------------------------------
__global__ void k_zero_meta() {
    int tot1 = (LL + 1) * GG * DD;
    int total = tot1 + GG + NN;
    for (int i = blockIdx.x * blockDim.x + threadIdx.x; i < total; i += gridDim.x * blockDim.x) {
        if (i < tot1) g_pooled[i] = 0.f;
        else if (i < tot1 + GG) g_counts[i - tot1] = 0.f;
        else g_deg[i - tot1 - GG] = 0;
    }
}

__global__ void k_counts(const int* __restrict__ batch) {
    int n = blockIdx.x * blockDim.x + threadIdx.x;
    if (n < NN) atomicAdd(&g_counts[batch[n]], 1.0f);
}

__global__ void k_copy_pool0(const float* __restrict__ x, const int* __restrict__ batch) {
    long long t = (long long)blockIdx.x * blockDim.x + threadIdx.x;
    int n = (int)(t >> 5);
    int lane = (int)(t & 31);
    if (n >= NN) return;
    int g = batch[n];
    float4 v = reinterpret_cast<const float4*>(x)[(long long)n * 32 + lane];
    reinterpret_cast<float4*>(g_xcur)[(long long)n * 32 + lane] = v;
    red_v4(&g_pooled[g * DD + lane * 4], v.x, v.y, v.z, v.w);
}

// ---------------------------------------------------------------------------
// Weight packing: hi/lo tf32 split in fragment order (one-time).
__global__ void k_packw(const float* __restrict__ conv_w1, const float* __restrict__ conv_w2) {
    int idx = blockIdx.x * blockDim.x + threadIdx.x;   // [li][p][c]
    if (idx >= LL * 2 * 64 * DD) return;
    int c  = idx & 127;
    int p  = (idx >> 7) & 63;
    int li = idx >> 13;
    int l = li >> 1;
    const float* W = ((li & 1) ? conv_w2 : conv_w1) + (long long)l * DD * DD;
    int k0 = ((p >> 2) << 3) | (p & 3);
    float w0 = W[k0 * DD + c];
    float w1 = W[(k0 + 4) * DD + c];
    uint4 v;
    v.x = f2tf32(w0); v.z = f2tf32(w0 - __uint_as_float(v.x));
    v.y = f2tf32(w1); v.w = f2tf32(w1 - __uint_as_float(v.y));
    g_wpack[li][p * DD + c] = v;
}

// ---------------------------------------------------------------------------
// CSR build
__global__ void k_hist(const int* __restrict__ edge_index) {
    int e = blockIdx.x * blockDim.x + threadIdx.x;
    if (e < EE) atomicAdd(&g_deg[edge_index[EE + e]], 1);
}

__global__ void k_scan_part() {
    __shared__ int s[SCAN_B];
    int t = threadIdx.x;
    int idx = blockIdx.x * SCAN_B + t;
    int val = (idx < NN) ? g_deg[idx] : 0;
    s[t] = val;
    __syncthreads();
    #pragma unroll
    for (int d = 1; d < SCAN_B; d <<= 1) {
        int v = (t >= d) ? s[t - d] : 0;
        __syncthreads();
        s[t] += v;
        __syncthreads();
    }
    if (idx < NN) g_off[idx] = s[t] - val;
    if (t == SCAN_B - 1) g_bsum[blockIdx.x] = s[t];
}

__global__ void k_scan_tot() {
    if (threadIdx.x == 0) {
        int run = 0;
        for (int b = 0; b < SCAN_NBLK; b++) {
            int v = g_bsum[b];
            g_bsum[b] = run;
            run += v;
        }
        g_off[NN] = run;
    }
}

__global__ void k_scan_add() {
    int idx = blockIdx.x * SCAN_B + threadIdx.x;
    if (idx < NN) {
        int o = g_off[idx] + g_bsum[blockIdx.x];
        g_off[idx] = o;
        g_epos[idx] = o;
    }
}

__global__ void k_scatter(const int* __restrict__ edge_index,
                          const int* __restrict__ edge_attr) {
    int e = blockIdx.x * blockDim.x + threadIdx.x;
    if (e >= EE) return;
    int src = edge_index[e];
    int dst = edge_index[EE + e];
    int a0 = edge_attr[e * 3 + 0];
    int a1 = edge_attr[e * 3 + 1];
    int a2 = edge_attr[e * 3 + 2];
    int pos = atomicAdd(&g_epos[dst], 1);
    g_esrc[pos] = src;
    g_eattr[pos] = a0 | (a1 << 3) | (a2 << 6);
}

// ---------------------------------------------------------------------------
// Aggregation: one warp per node. g_aggr[n] = x[n] + sum_e relu(x[src]+emb)
__global__ void __launch_bounds__(256)
k_aggr(const float* __restrict__ bond_layer) {
    int n = blockIdx.x * (blockDim.x >> 5) + (threadIdx.x >> 5);
    int lane = threadIdx.x & 31;
    if (n >= NN) return;
    int beg = g_off[n];
    int end = g_off[n + 1];
    const float4* b4 = reinterpret_cast<const float4*>(bond_layer);
    const float4* xc = reinterpret_cast<const float4*>(g_xcur);
    float4 acc = xc[(long long)n * 32 + lane];
    #pragma unroll 2
    for (int e = beg; e < end; e++) {
        int src = g_esrc[e];
        int p = g_eattr[e];
        float4 e0 = b4[(p & 7) * 32 + lane];
        float4 e1 = b4[(8 + ((p >> 3) & 7)) * 32 + lane];
        float4 e2 = b4[(16 + ((p >> 6) & 7)) * 32 + lane];
        float4 xv = xc[(long long)src * 32 + lane];
        acc.x += fmaxf(xv.x + e0.x + e1.x + e2.x, 0.f);
        acc.y += fmaxf(xv.y + e0.y + e1.y + e2.y, 0.f);
        acc.z += fmaxf(xv.z + e0.z + e1.z + e2.z, 0.f);
        acc.w += fmaxf(xv.w + e0.w + e1.w + e2.w, 0.f);
    }
    reinterpret_cast<float4*>(g_aggr)[(long long)n * 32 + lane] = acc;
}

// ---------------------------------------------------------------------------
// Tensor-core GEMM: A tile in smem (66 KB -> 2 blocks/SM), W fragments read
// directly from packed global (L1-resident after first touch).
// MODE 0: in = g_aggr, out = g_h1      (wi = layer*2)
// MODE 1: in = g_h1,   out = g_xcur, pool into g_pooled[layer+1]  (wi = layer*2+1)
// 256 threads: warp w: wm = w&3 (rows of 32), wn = w>>2 (cols of 64).
template <int MODE>
__global__ void __launch_bounds__(256, 2)
k_gemm_tc(const float* __restrict__ bias,
          const float* __restrict__ gamma, const float* __restrict__ beta,
          const float* __restrict__ mean, const float* __restrict__ var,
          const int* __restrict__ batch, int layer) {
    __shared__ uint32_t sA[DD * SA_STRIDE];   // [128][132] tf32

    const int tid = threadIdx.x;
    const int m0 = blockIdx.x * 128;

    // ---- Load A tile, convert to tf32 ----
    {
        const float4* Ag = reinterpret_cast<const float4*>(MODE == 0 ? g_aggr : g_h1);
        #pragma unroll
        for (int i = 0; i < 16; i++) {
            int idx = tid + i * 256;        // 0..4095
            int row = idx >> 5;
            int c4  = idx & 31;
            int m = m0 + row;
            float4 v = make_float4(0.f, 0.f, 0.f, 0.f);
            if (m < NN) v = Ag[(long long)m * 32 + c4];
            uint4 tv;
            tv.x = f2tf32(v.x); tv.y = f2tf32(v.y); tv.z = f2tf32(v.z); tv.w = f2tf32(v.w);
            *reinterpret_cast<uint4*>(&sA[row * SA_STRIDE + c4 * 4]) = tv;
        }
    }
    __syncthreads();

    const int w    = tid >> 5;
    const int lane = tid & 31;
    const int wm   = w & 3;       // row group of 32
    const int wn   = w >> 2;      // col group of 64 (0..1)
    const int gid  = lane >> 2;   // 0..7
    const int tig  = lane & 3;    // 0..3

    float acc[2][8][4];
    #pragma unroll
    for (int mi = 0; mi < 2; mi++)
        #pragma unroll
        for (int ni = 0; ni < 8; ni++)
            #pragma unroll
            for (int r = 0; r < 4; r++) acc[mi][ni][r] = 0.f;

    const uint32_t* aRow0  = sA + (wm * 32 + gid) * SA_STRIDE;
    const uint32_t* aRow0b = aRow0 + 8 * SA_STRIDE;
    const uint32_t* aRow1  = sA + (wm * 32 + 16 + gid) * SA_STRIDE;
    const uint32_t* aRow1b = aRow1 + 8 * SA_STRIDE;
    const int colbase = wn * 64 + gid;
    const uint4* __restrict__ Wp = g_wpack[layer * 2 + MODE];

    #pragma unroll 4
    for (int kk = 0; kk < 16; kk++) {
        int k0 = kk * 8 + tig;
        uint32_t a0[4], a1[4];
        a0[0] = aRow0[k0];  a0[1] = aRow0b[k0];  a0[2] = aRow0[k0 + 4];  a0[3] = aRow0b[k0 + 4];
        a1[0] = aRow1[k0];  a1[1] = aRow1b[k0];  a1[2] = aRow1[k0 + 4];  a1[3] = aRow1b[k0 + 4];
        const uint4* wrow = Wp + (kk * 4 + tig) * DD;
        #pragma unroll
        for (int ni = 0; ni < 8; ni++) {
            uint4 wv = __ldg(&wrow[colbase + ni * 8]);
            mma_tf32(acc[0][ni], a0, wv.x, wv.y);
            mma_tf32(acc[0][ni], a0, wv.z, wv.w);
            mma_tf32(acc[1][ni], a1, wv.x, wv.y);
            mma_tf32(acc[1][ni], a1, wv.z, wv.w);
        }
    }

    // ---- Epilogue: bias + BN + relu, store, optional pooling ----
    float* Cout = (MODE == 0) ? g_h1 : g_xcur;
    #pragma unroll
    for (int ni = 0; ni < 8; ni++) {
        int c = wn * 64 + ni * 8 + tig * 2;
        float2 bi = *reinterpret_cast<const float2*>(bias + c);
        float2 ga = *reinterpret_cast<const float2*>(gamma + c);
        float2 be = *reinterpret_cast<const float2*>(beta + c);
        float2 me = *reinterpret_cast<const float2*>(mean + c);
        float2 va = *reinterpret_cast<const float2*>(var + c);
        float scx = ga.x * rsqrtf(va.x + BN_EPS);
        float scy = ga.y * rsqrtf(va.y + BN_EPS);
        float shx = be.x - me.x * scx;
        float shy = be.y - me.y * scy;
        #pragma unroll
        for (int mi = 0; mi < 2; mi++) {
            #pragma unroll
            for (int h = 0; h < 2; h++) {
                int row = m0 + wm * 32 + mi * 16 + gid + h * 8;
                if (row < NN) {
                    float r0 = fmaxf((acc[mi][ni][h * 2 + 0] + bi.x) * scx + shx, 0.f);
                    float r1 = fmaxf((acc[mi][ni][h * 2 + 1] + bi.y) * scy + shy, 0.f);
                    *reinterpret_cast<float2*>(&Cout[(long long)row * DD + c]) = make_float2(r0, r1);
                    if (MODE == 1) {
                        int g = batch[row];
                        red_v2(&g_pooled[(layer + 1) * GG * DD + g * DD + c], r0, r1);
                    }
                }
            }
        }
    }
}

// ---------------------------------------------------------------------------
__global__ void k_head(const float* __restrict__ fc_w, const float* __restrict__ fc_b,
                       float* __restrict__ out) {
    __shared__ float sp[(LL + 1) * DD];
    int g = blockIdx.x;
    float inv = 1.0f / fmaxf(g_counts[g], 1.0f);
    for (int i = threadIdx.x; i < (LL + 1) * DD; i += blockDim.x) {
        int l = i >> 7;
        int d = i & 127;
        sp[i] = g_pooled[l * GG * DD + g * DD + d] * inv;
    }
    __syncthreads();
    int o = threadIdx.x;
    if (o < OO) {
        float s = 0.f;
        #pragma unroll
        for (int l = 0; l < LL + 1; l++) {
            float partial = 0.f;
            for (int d = 0; d < DD; d++) {
                partial += sp[l * DD + d] * fc_w[(l * DD + d) * OO + o];
            }
            s += partial + fc_b[l * OO + o];
        }
        out[g * OO + o] = s;
    }
}

// ---------------------------------------------------------------------------
extern "C" void kernel_launch(void* const* d_in, const int* in_sizes, int n_in,
                              void* d_out, int out_size) {
    const float* x          = (const float*)d_in[0];
    const int*   edge_index = (const int*)d_in[1];
    const int*   edge_attr  = (const int*)d_in[2];
    const int*   batch      = (const int*)d_in[3];
    const float* bond_emb   = (const float*)d_in[4];
    const float* conv_w1    = (const float*)d_in[5];
    const float* conv_b1    = (const float*)d_in[6];
    const float* cbn_g      = (const float*)d_in[7];
    const float* cbn_b      = (const float*)d_in[8];
    const float* cbn_m      = (const float*)d_in[9];
    const float* cbn_v      = (const float*)d_in[10];
    const float* conv_w2    = (const float*)d_in[11];
    const float* conv_b2    = (const float*)d_in[12];
    const float* bn_g       = (const float*)d_in[13];
    const float* bn_b       = (const float*)d_in[14];
    const float* bn_m       = (const float*)d_in[15];
    const float* bn_v       = (const float*)d_in[16];
    const float* fc_w       = (const float*)d_in[17];
    const float* fc_b       = (const float*)d_in[18];
    float* out = (float*)d_out;

    // Prologue
    k_zero_meta<<<512, 256>>>();
    k_packw<<<(LL * 2 * 64 * DD + 255) / 256, 256>>>(conv_w1, conv_w2);
    k_counts<<<(NN + 255) / 256, 256>>>(batch);
    {
        long long tot = (long long)NN * 32;
        k_copy_pool0<<<(int)((tot + 255) / 256), 256>>>(x, batch);
    }
    k_hist<<<(EE + 255) / 256, 256>>>(edge_index);
    k_scan_part<<<SCAN_NBLK, SCAN_B>>>();
    k_scan_tot<<<1, 32>>>();
    k_scan_add<<<SCAN_NBLK, SCAN_B>>>();
    k_scatter<<<(EE + 255) / 256, 256>>>(edge_index, edge_attr);

    const int gemm_grid = (NN + 127) / 128;
    const int aggr_grid = (NN + 7) / 8;

    for (int i = 0; i < LL; i++) {
        k_aggr<<<aggr_grid, 256>>>(bond_emb + (long long)i * 3 * 8 * DD);
        k_gemm_tc<0><<<gemm_grid, 256>>>(
            conv_b1 + i * DD,
            cbn_g + i * DD, cbn_b + i * DD, cbn_m + i * DD, cbn_v + i * DD,
            batch, i);
        k_gemm_tc<1><<<gemm_grid, 256>>>(
            conv_b2 + i * DD,
            bn_g + i * DD, bn_b + i * DD, bn_m + i * DD, bn_v + i * DD,
            batch, i);
    }

    k_head<<<GG, 128>>>(fc_w, fc_b, out);
    (void)in_sizes; (void)n_in; (void)out_size;
}

// round 16
// speedup vs baseline: 1.3628x; 1.3628x over previous
#include <cuda_runtime.h>
#include <cuda_bf16.h>
#include <cstdint>

#define NN 50000
#define EE 600000
#define DD 128
#define GG 256
#define OO 10
#define LL 5
#define BN_EPS 1e-5f

// Scratch (static device globals — no runtime allocation).
// NOTE: never reference these symbols in HOST code (ATS resolves the host
// shadow silently on GB300). Device code only.
__device__ float g_xcur[NN * DD];
__device__ float g_aggr[NN * DD];
__device__ float g_h1[NN * DD];
__device__ float g_pooled[(LL + 1) * GG * DD];
__device__ float g_counts[GG];

// Packed bf16 hi/lo weights in B-fragment lane order:
// g_wpackb[li][(kk*16 + nf)*32 + lane] = uint4(b0h, b1h, b0l, b1l)
// kk = k16 step (0..7), nf = 8-col group (0..15), lane = 0..31.
__device__ uint4 g_wpackb[LL * 2][8 * 16 * 32];

// CSR scratch
__device__ int g_deg[NN];
__device__ int g_off[NN + 1];
__device__ int g_epos[NN];
__device__ int g_bsum[128];
__device__ int g_esrc[EE];
__device__ int g_eattr[EE];   // packed a0 | a1<<3 | a2<<6

#define SCAN_B 512
#define SCAN_NBLK ((NN + SCAN_B - 1) / SCAN_B)   // 98

// A-tile geometry (bf16): stride 136 elements = 272 bytes per row
#define A_STRIDE_E 136
#define A_TILE_BYTES (DD * A_STRIDE_E * 2)   // 34816 per tile (hi or lo)

// ---------------------------------------------------------------------------
__device__ __forceinline__ void mma_bf16(float* c, const uint32_t* a, uint32_t b0, uint32_t b1) {
    asm volatile(
        "mma.sync.aligned.m16n8k16.row.col.f32.bf16.bf16.f32 "
        "{%0,%1,%2,%3}, {%4,%5,%6,%7}, {%8,%9}, {%0,%1,%2,%3};"
        : "+f"(c[0]), "+f"(c[1]), "+f"(c[2]), "+f"(c[3])
        : "r"(a[0]), "r"(a[1]), "r"(a[2]), "r"(a[3]), "r"(b0), "r"(b1));
}

__device__ __forceinline__ void ldsm_x4(uint32_t& r0, uint32_t& r1, uint32_t& r2, uint32_t& r3,
                                        uint32_t addr) {
    asm volatile("ldmatrix.sync.aligned.m8n8.x4.shared.b16 {%0,%1,%2,%3}, [%4];"
                 : "=r"(r0), "=r"(r1), "=r"(r2), "=r"(r3) : "r"(addr));
}

__device__ __forceinline__ void red_v4(float* addr, float x, float y, float z, float w) {
    asm volatile("red.global.add.v4.f32 [%0], {%1,%2,%3,%4};"
                 :: "l"(addr), "f"(x), "f"(y), "f"(z), "f"(w) : "memory");
}

__device__ __forceinline__ void red_v2(float* addr, float x, float y) {
    asm volatile("red.global.add.v2.f32 [%0], {%1,%2};"
                 :: "l"(addr), "f"(x), "f"(y) : "memory");
}

__device__ __forceinline__ uint32_t bf16pair(float a, float b) {
    __nv_bfloat162 p(__float2bfloat16_rn(a), __float2bfloat16_rn(b));
    return *reinterpret_cast<uint32_t*>(&p);
}

// ---------------------------------------------------------------------------
__global__ void k_zero_meta() {
    int tot1 = (LL + 1) * GG * DD;
    int total = tot1 + GG + NN;
    for (int i = blockIdx.x * blockDim.x + threadIdx.x; i < total; i += gridDim.x * blockDim.x) {
        if (i < tot1) g_pooled[i] = 0.f;
        else if (i < tot1 + GG) g_counts[i - tot1] = 0.f;
        else g_deg[i - tot1 - GG] = 0;
    }
}

__global__ void k_counts(const int* __restrict__ batch) {
    int n = blockIdx.x * blockDim.x + threadIdx.x;
    if (n < NN) atomicAdd(&g_counts[batch[n]], 1.0f);
}

__global__ void k_copy_pool0(const float* __restrict__ x, const int* __restrict__ batch) {
    long long t = (long long)blockIdx.x * blockDim.x + threadIdx.x;
    int n = (int)(t >> 5);
    int lane = (int)(t & 31);
    if (n >= NN) return;
    int g = batch[n];
    float4 v = reinterpret_cast<const float4*>(x)[(long long)n * 32 + lane];
    reinterpret_cast<float4*>(g_xcur)[(long long)n * 32 + lane] = v;
    red_v4(&g_pooled[g * DD + lane * 4], v.x, v.y, v.z, v.w);
}

// ---------------------------------------------------------------------------
// Pack weights as bf16 hi/lo B-fragments (one-time, 40960 threads).
__global__ void k_packw(const float* __restrict__ conv_w1, const float* __restrict__ conv_w2) {
    int idx = blockIdx.x * blockDim.x + threadIdx.x;   // [li][kk][nf][lane]
    if (idx >= LL * 2 * 8 * 16 * 32) return;
    int lane = idx & 31;
    int nf   = (idx >> 5) & 15;
    int kk   = (idx >> 9) & 7;
    int li   = idx >> 12;
    int l = li >> 1;
    const float* W = ((li & 1) ? conv_w2 : conv_w1) + (long long)l * DD * DD;
    int n  = nf * 8 + (lane >> 2);
    int k0 = kk * 16 + (lane & 3) * 2;
    float w00 = W[(k0 + 0) * DD + n];
    float w01 = W[(k0 + 1) * DD + n];
    float w10 = W[(k0 + 8) * DD + n];
    float w11 = W[(k0 + 9) * DD + n];
    float h00 = __bfloat162float(__float2bfloat16_rn(w00));
    float h01 = __bfloat162float(__float2bfloat16_rn(w01));
    float h10 = __bfloat162float(__float2bfloat16_rn(w10));
    float h11 = __bfloat162float(__float2bfloat16_rn(w11));
    uint4 v;
    v.x = bf16pair(w00, w01);               // b0 hi
    v.y = bf16pair(w10, w11);               // b1 hi
    v.z = bf16pair(w00 - h00, w01 - h01);   // b0 lo
    v.w = bf16pair(w10 - h10, w11 - h11);   // b1 lo
    g_wpackb[li][(kk * 16 + nf) * 32 + lane] = v;
}

// ---------------------------------------------------------------------------
// CSR build
__global__ void k_hist(const int* __restrict__ edge_index) {
    int e = blockIdx.x * blockDim.x + threadIdx.x;
    if (e < EE) atomicAdd(&g_deg[edge_index[EE + e]], 1);
}

__global__ void k_scan_part() {
    __shared__ int s[SCAN_B];
    int t = threadIdx.x;
    int idx = blockIdx.x * SCAN_B + t;
    int val = (idx < NN) ? g_deg[idx] : 0;
    s[t] = val;
    __syncthreads();
    #pragma unroll
    for (int d = 1; d < SCAN_B; d <<= 1) {
        int v = (t >= d) ? s[t - d] : 0;
        __syncthreads();
        s[t] += v;
        __syncthreads();
    }
    if (idx < NN) g_off[idx] = s[t] - val;
    if (t == SCAN_B - 1) g_bsum[blockIdx.x] = s[t];
}

__global__ void k_scan_tot() {
    if (threadIdx.x == 0) {
        int run = 0;
        for (int b = 0; b < SCAN_NBLK; b++) {
            int v = g_bsum[b];
            g_bsum[b] = run;
            run += v;
        }
        g_off[NN] = run;
    }
}

__global__ void k_scan_add() {
    int idx = blockIdx.x * SCAN_B + threadIdx.x;
    if (idx < NN) {
        int o = g_off[idx] + g_bsum[blockIdx.x];
        g_off[idx] = o;
        g_epos[idx] = o;
    }
}

__global__ void k_scatter(const int* __restrict__ edge_index,
                          const int* __restrict__ edge_attr) {
    int e = blockIdx.x * blockDim.x + threadIdx.x;
    if (e >= EE) return;
    int src = edge_index[e];
    int dst = edge_index[EE + e];
    int a0 = edge_attr[e * 3 + 0];
    int a1 = edge_attr[e * 3 + 1];
    int a2 = edge_attr[e * 3 + 2];
    int pos = atomicAdd(&g_epos[dst], 1);
    g_esrc[pos] = src;
    g_eattr[pos] = a0 | (a1 << 3) | (a2 << 6);
}

// ---------------------------------------------------------------------------
// Aggregation: one warp per node. g_aggr[n] = x[n] + sum_e relu(x[src]+emb)
__global__ void __launch_bounds__(256)
k_aggr(const float* __restrict__ bond_layer) {
    int n = blockIdx.x * (blockDim.x >> 5) + (threadIdx.x >> 5);
    int lane = threadIdx.x & 31;
    if (n >= NN) return;
    int beg = g_off[n];
    int end = g_off[n + 1];
    const float4* b4 = reinterpret_cast<const float4*>(bond_layer);
    const float4* xc = reinterpret_cast<const float4*>(g_xcur);
    float4 acc = xc[(long long)n * 32 + lane];
    #pragma unroll 2
    for (int e = beg; e < end; e++) {
        int src = g_esrc[e];
        int p = g_eattr[e];
        float4 e0 = b4[(p & 7) * 32 + lane];
        float4 e1 = b4[(8 + ((p >> 3) & 7)) * 32 + lane];
        float4 e2 = b4[(16 + ((p >> 6) & 7)) * 32 + lane];
        float4 xv = xc[(long long)src * 32 + lane];
        acc.x += fmaxf(xv.x + e0.x + e1.x + e2.x, 0.f);
        acc.y += fmaxf(xv.y + e0.y + e1.y + e2.y, 0.f);
        acc.z += fmaxf(xv.z + e0.z + e1.z + e2.z, 0.f);
        acc.w += fmaxf(xv.w + e0.w + e1.w + e2.w, 0.f);
    }
    reinterpret_cast<float4*>(g_aggr)[(long long)n * 32 + lane] = acc;
}

// ---------------------------------------------------------------------------
// bf16 split tensor-core GEMM. A hi/lo tiles in smem (ldmatrix), W hi/lo
// fragments from packed global (one LDG.128 per fragment, batch-issued).
// MODE 0: in = g_aggr, out = g_h1
// MODE 1: in = g_h1,   out = g_xcur, pool into g_pooled[layer+1]
// 256 threads: warp w: wm = w&3 (rows of 32), wn = w>>2 (cols of 64).
template <int MODE>
__global__ void __launch_bounds__(256, 2)
k_gemm_tc(const float* __restrict__ bias,
          const float* __restrict__ gamma, const float* __restrict__ beta,
          const float* __restrict__ mean, const float* __restrict__ var,
          const int* __restrict__ batch, int layer) {
    extern __shared__ uint8_t smem8[];   // Ah tile then Al tile

    const int tid = threadIdx.x;
    const int m0 = blockIdx.x * 128;

    // ---- Load A tile, split into bf16 hi/lo ----
    {
        const float4* Ag = reinterpret_cast<const float4*>(MODE == 0 ? g_aggr : g_h1);
        #pragma unroll
        for (int i = 0; i < 16; i++) {
            int idx = tid + i * 256;        // 0..4095
            int row = idx >> 5;
            int c4  = idx & 31;             // float4 index within row
            int m = m0 + row;
            float4 v = make_float4(0.f, 0.f, 0.f, 0.f);
            if (m < NN) v = Ag[(long long)m * 32 + c4];
            float hx = __bfloat162float(__float2bfloat16_rn(v.x));
            float hy = __bfloat162float(__float2bfloat16_rn(v.y));
            float hz = __bfloat162float(__float2bfloat16_rn(v.z));
            float hw = __bfloat162float(__float2bfloat16_rn(v.w));
            uint2 hi = make_uint2(bf16pair(v.x, v.y), bf16pair(v.z, v.w));
            uint2 lo = make_uint2(bf16pair(v.x - hx, v.y - hy), bf16pair(v.z - hz, v.w - hw));
            int boff = row * (A_STRIDE_E * 2) + c4 * 8;
            *reinterpret_cast<uint2*>(smem8 + boff) = hi;
            *reinterpret_cast<uint2*>(smem8 + A_TILE_BYTES + boff) = lo;
        }
    }
    __syncthreads();

    const int w    = tid >> 5;
    const int lane = tid & 31;
    const int wm   = w & 3;       // row group of 32
    const int wn   = w >> 2;      // col group of 64 (0..1)
    const int gid  = lane >> 2;   // 0..7
    const int tig  = lane & 3;    // 0..3

    float acc[2][8][4];
    #pragma unroll
    for (int mi = 0; mi < 2; mi++)
        #pragma unroll
        for (int ni = 0; ni < 8; ni++)
            #pragma unroll
            for (int r = 0; r < 4; r++) acc[mi][ni][r] = 0.f;

    // ldmatrix per-lane base address: row = wm*32 + (lane&15), col-half (lane>>4)*8
    uint32_t smem_base = (uint32_t)__cvta_generic_to_shared(smem8);
    uint32_t a_base = smem_base + (wm * 32 + (lane & 15)) * (A_STRIDE_E * 2)
                      + ((lane >> 4) & 1) * 16;
    const uint4* __restrict__ Wp = g_wpackb[layer * 2 + MODE] + wn * 8 * 32 + lane;

    #pragma unroll 4
    for (int kk = 0; kk < 8; kk++) {
        // Batch-issue the 8 W fragment loads (independent LDG.128s)
        uint4 wv[8];
        const uint4* wk = Wp + kk * 16 * 32;
        #pragma unroll
        for (int ni = 0; ni < 8; ni++) wv[ni] = __ldg(wk + ni * 32);

        // A fragments: hi and lo, both 16-row groups
        uint32_t ah0[4], ah1[4], al0[4], al1[4];
        uint32_t koff = kk * 32;  // kk*16 elems * 2B
        ldsm_x4(ah0[0], ah0[1], ah0[2], ah0[3], a_base + koff);
        ldsm_x4(ah1[0], ah1[1], ah1[2], ah1[3], a_base + 16 * (A_STRIDE_E * 2) + koff);
        ldsm_x4(al0[0], al0[1], al0[2], al0[3], a_base + A_TILE_BYTES + koff);
        ldsm_x4(al1[0], al1[1], al1[2], al1[3], a_base + A_TILE_BYTES + 16 * (A_STRIDE_E * 2) + koff);

        #pragma unroll
        for (int ni = 0; ni < 8; ni++) {
            mma_bf16(acc[0][ni], ah0, wv[ni].x, wv[ni].y);   // Ah@Wh
            mma_bf16(acc[0][ni], ah0, wv[ni].z, wv[ni].w);   // Ah@Wl
            mma_bf16(acc[0][ni], al0, wv[ni].x, wv[ni].y);   // Al@Wh
            mma_bf16(acc[1][ni], ah1, wv[ni].x, wv[ni].y);
            mma_bf16(acc[1][ni], ah1, wv[ni].z, wv[ni].w);
            mma_bf16(acc[1][ni], al1, wv[ni].x, wv[ni].y);
        }
    }

    // ---- Epilogue: bias + BN + relu, store, optional pooling ----
    // D frag: c0 = D[gid][2t], c1 = D[gid][2t+1], c2 = D[gid+8][2t], c3 = D[gid+8][2t+1]
    float* Cout = (MODE == 0) ? g_h1 : g_xcur;
    #pragma unroll
    for (int ni = 0; ni < 8; ni++) {
        int c = wn * 64 + ni * 8 + tig * 2;
        float2 bi = *reinterpret_cast<const float2*>(bias + c);
        float2 ga = *reinterpret_cast<const float2*>(gamma + c);
        float2 be = *reinterpret_cast<const float2*>(beta + c);
        float2 me = *reinterpret_cast<const float2*>(mean + c);
        float2 va = *reinterpret_cast<const float2*>(var + c);
        float scx = ga.x * rsqrtf(va.x + BN_EPS);
        float scy = ga.y * rsqrtf(va.y + BN_EPS);
        float shx = be.x - me.x * scx;
        float shy = be.y - me.y * scy;
        #pragma unroll
        for (int mi = 0; mi < 2; mi++) {
            #pragma unroll
            for (int h = 0; h < 2; h++) {
                int row = m0 + wm * 32 + mi * 16 + gid + h * 8;
                if (row < NN) {
                    float r0 = fmaxf((acc[mi][ni][h * 2 + 0] + bi.x) * scx + shx, 0.f);
                    float r1 = fmaxf((acc[mi][ni][h * 2 + 1] + bi.y) * scy + shy, 0.f);
                    *reinterpret_cast<float2*>(&Cout[(long long)row * DD + c]) = make_float2(r0, r1);
                    if (MODE == 1) {
                        int g = batch[row];
                        red_v2(&g_pooled[(layer + 1) * GG * DD + g * DD + c], r0, r1);
                    }
                }
            }
        }
    }
}

// ---------------------------------------------------------------------------
__global__ void k_head(const float* __restrict__ fc_w, const float* __restrict__ fc_b,
                       float* __restrict__ out) {
    __shared__ float sp[(LL + 1) * DD];
    int g = blockIdx.x;
    float inv = 1.0f / fmaxf(g_counts[g], 1.0f);
    for (int i = threadIdx.x; i < (LL + 1) * DD; i += blockDim.x) {
        int l = i >> 7;
        int d = i & 127;
        sp[i] = g_pooled[l * GG * DD + g * DD + d] * inv;
    }
    __syncthreads();
    int o = threadIdx.x;
    if (o < OO) {
        float s = 0.f;
        #pragma unroll
        for (int l = 0; l < LL + 1; l++) {
            float partial = 0.f;
            for (int d = 0; d < DD; d++) {
                partial += sp[l * DD + d] * fc_w[(l * DD + d) * OO + o];
            }
            s += partial + fc_b[l * OO + o];
        }
        out[g * OO + o] = s;
    }
}

// ---------------------------------------------------------------------------
extern "C" void kernel_launch(void* const* d_in, const int* in_sizes, int n_in,
                              void* d_out, int out_size) {
    const float* x          = (const float*)d_in[0];
    const int*   edge_index = (const int*)d_in[1];
    const int*   edge_attr  = (const int*)d_in[2];
    const int*   batch      = (const int*)d_in[3];
    const float* bond_emb   = (const float*)d_in[4];
    const float* conv_w1    = (const float*)d_in[5];
    const float* conv_b1    = (const float*)d_in[6];
    const float* cbn_g      = (const float*)d_in[7];
    const float* cbn_b      = (const float*)d_in[8];
    const float* cbn_m      = (const float*)d_in[9];
    const float* cbn_v      = (const float*)d_in[10];
    const float* conv_w2    = (const float*)d_in[11];
    const float* conv_b2    = (const float*)d_in[12];
    const float* bn_g       = (const float*)d_in[13];
    const float* bn_b       = (const float*)d_in[14];
    const float* bn_m       = (const float*)d_in[15];
    const float* bn_v       = (const float*)d_in[16];
    const float* fc_w       = (const float*)d_in[17];
    const float* fc_b       = (const float*)d_in[18];
    float* out = (float*)d_out;

    const int smem_bytes = 2 * A_TILE_BYTES;   // 69632
    static bool attr_done = false;
    if (!attr_done) {
        cudaFuncSetAttribute(k_gemm_tc<0>, cudaFuncAttributeMaxDynamicSharedMemorySize, smem_bytes);
        cudaFuncSetAttribute(k_gemm_tc<1>, cudaFuncAttributeMaxDynamicSharedMemorySize, smem_bytes);
        attr_done = true;
    }

    // Prologue
    k_zero_meta<<<512, 256>>>();
    k_packw<<<(LL * 2 * 8 * 16 * 32 + 255) / 256, 256>>>(conv_w1, conv_w2);
    k_counts<<<(NN + 255) / 256, 256>>>(batch);
    {
        long long tot = (long long)NN * 32;
        k_copy_pool0<<<(int)((tot + 255) / 256), 256>>>(x, batch);
    }
    k_hist<<<(EE + 255) / 256, 256>>>(edge_index);
    k_scan_part<<<SCAN_NBLK, SCAN_B>>>();
    k_scan_tot<<<1, 32>>>();
    k_scan_add<<<SCAN_NBLK, SCAN_B>>>();
    k_scatter<<<(EE + 255) / 256, 256>>>(edge_index, edge_attr);

    const int gemm_grid = (NN + 127) / 128;
    const int aggr_grid = (NN + 7) / 8;

    for (int i = 0; i < LL; i++) {
        k_aggr<<<aggr_grid, 256>>>(bond_emb + (long long)i * 3 * 8 * DD);
        k_gemm_tc<0><<<gemm_grid, 256, smem_bytes>>>(
            conv_b1 + i * DD,
            cbn_g + i * DD, cbn_b + i * DD, cbn_m + i * DD, cbn_v + i * DD,
            batch, i);
        k_gemm_tc<1><<<gemm_grid, 256, smem_bytes>>>(
            conv_b2 + i * DD,
            bn_g + i * DD, bn_b + i * DD, bn_m + i * DD, bn_v + i * DD,
            batch, i);
    }

    k_head<<<GG, 128>>>(fc_w, fc_b, out);
    (void)in_sizes; (void)n_in; (void)out_size;
}